// round 12
// baseline (speedup 1.0000x reference)
#include <cuda_runtime.h>
#include <cstdint>

// ---------------------------------------------------------------------------
// N=100000, 512 -> 16 -> 40, E=3.2M int32 edges.
// out = log_softmax( segsum(relu(segsum((xW1)[src])+b1)[src]) @ W2 + b2 )
// (W2 hoisted past the scatter by linearity of segment_sum.)
//
// R12: fixes R11 crash (float4 ops on 68B-strided smem rows = misaligned).
// x staging now: coalesced loads (lane&1 = float4-in-row, lane>>1 = row),
// scalar STS/LDS into stride-9 tile (9 coprime 32 -> conflict-free reads).
// W broadcast LDS.128 + FFMA2 col-pairs unchanged. occ target ~32 warps/SM.
// RULE: __device__ globals only referenced in device code (ATS trap).
// ---------------------------------------------------------------------------

#define NNODES 100000
#define HID 16
#define NEDGES 3200000
#define NB_SCAN 391         // ceil(NNODES/256)

__device__ __align__(16) float g_h1  [NNODES * HID];
__device__ __align__(16) float g_agg1[NNODES * HID];
__device__ __align__(16) float g_agg2[NNODES * HID];
__device__ int g_cnt   [NNODES];
__device__ int g_rowptr[NNODES + 1];
__device__ int g_cursor[NNODES];
__device__ int g_esrc  [NEDGES];
__device__ int g_blksum[512];
__device__ int g_is64;

// packed f32x2 ops (PTX-only)
#define FMA_F32X2(d, a, b, c) \
    asm("fma.rn.f32x2 %0, %1, %2, %3;" : "=l"(d) : "l"(a), "l"(b), "l"(c))
#define ADD_F32X2(d, a, b) \
    asm("add.rn.f32x2 %0, %1, %2;" : "=l"(d) : "l"(a), "l"(b))
#define PACK2(d, s) \
    asm("mov.b64 %0, {%1, %1};" : "=l"(d) : "r"(__float_as_uint(s)))

// ---------------------------------------------------------------------------
__device__ __forceinline__ int edge_at(const int* ei, int idx, int E, int half) {
    if (g_is64) {
        const long long* ll = reinterpret_cast<const long long*>(ei);
        return (int)__ldg(ll + (size_t)half * E + idx);
    }
    return __ldg(ei + (size_t)half * E + idx);
}

__global__ void detect_kernel(const int* __restrict__ ei) {
    __shared__ int any_nonzero;
    if (threadIdx.x == 0) any_nonzero = 0;
    __syncthreads();
    int bad = 0;
    for (int w = 1 + 2 * threadIdx.x; w < 2048; w += 2 * blockDim.x)
        if (ei[w] != 0) bad = 1;
    if (bad) atomicOr(&any_nonzero, 1);
    __syncthreads();
    if (threadIdx.x == 0) g_is64 = (any_nonzero == 0) ? 1 : 0;
}

// ---------------------------------------------------------------------------
// CSR build
// ---------------------------------------------------------------------------
__global__ void zero_cnt_kernel() {
    int i = blockIdx.x * blockDim.x + threadIdx.x;
    if (i < NNODES) g_cnt[i] = 0;
}

__global__ void hist_kernel(const int* __restrict__ ei, int E) {
    int e = blockIdx.x * blockDim.x + threadIdx.x;
    if (e >= E) return;
    int d = edge_at(ei, e, E, 1);
    atomicAdd(&g_cnt[d], 1);
}

__global__ void scan1_kernel() {
    __shared__ int buf[2][256];
    int t = threadIdx.x, b = blockIdx.x;
    int i = b * 256 + t;
    int v = (i < NNODES) ? g_cnt[i] : 0;
    int cur = 0;
    buf[0][t] = v;
    __syncthreads();
#pragma unroll
    for (int off = 1; off < 256; off <<= 1) {
        int x = buf[cur][t];
        if (t >= off) x += buf[cur][t - off];
        buf[cur ^ 1][t] = x;
        cur ^= 1;
        __syncthreads();
    }
    int incl = buf[cur][t];
    if (i < NNODES) g_rowptr[i] = incl - v;
    if (t == 255) g_blksum[b] = incl;
}

__global__ void scan2_kernel() {
    __shared__ int buf[2][512];
    int t = threadIdx.x;
    int v = (t < NB_SCAN) ? g_blksum[t] : 0;
    int cur = 0;
    buf[0][t] = v;
    __syncthreads();
#pragma unroll
    for (int off = 1; off < 512; off <<= 1) {
        int x = buf[cur][t];
        if (t >= off) x += buf[cur][t - off];
        buf[cur ^ 1][t] = x;
        cur ^= 1;
        __syncthreads();
    }
    if (t < NB_SCAN) g_blksum[t] = buf[cur][t] - v;
}

__global__ void scan3_kernel() {
    int i = blockIdx.x * blockDim.x + threadIdx.x;
    if (i < NNODES) {
        int r = g_rowptr[i] + g_blksum[i >> 8];
        g_rowptr[i] = r;
        g_cursor[i] = r;
    }
    if (i == 0) g_rowptr[NNODES] = NEDGES;
}

__global__ void fill_kernel(const int* __restrict__ ei, int E) {
    int e = blockIdx.x * blockDim.x + threadIdx.x;
    if (e >= E) return;
    int s = edge_at(ei, e, E, 0);
    int d = edge_at(ei, e, E, 1);
    int pos = atomicAdd(&g_cursor[d], 1);
    g_esrc[pos] = s;
}

// ---------------------------------------------------------------------------
// 1) h1 = x @ W1 — one row/thread, 256 thr/block.
//    Per 8-k chunk: coalesced LDG (f4=lane&1, r=lane>>1; 16 rows x 32B),
//    scalar STS/LDS via stride-9 smem tile; W broadcast LDS.128; FFMA2.
// ---------------------------------------------------------------------------
#define XS_STRIDE 9
__global__ void __launch_bounds__(256) gemm1_kernel(const float* __restrict__ x,
                                                    const float* __restrict__ W1) {
    __shared__ __align__(16) float Ws[8192];                 // W row-major [k][16]
    __shared__ float Xs[8][32 * XS_STRIDE];                  // per-warp 32 rows x 8 k

    int tid = threadIdx.x;
    for (int i = tid; i < 8192; i += 256)
        Ws[i] = W1[i];
    __syncthreads();

    int lane = tid & 31;
    int wrp  = tid >> 5;
    int row  = blockIdx.x * 256 + wrp * 32 + lane;
    int rbase = blockIdx.x * 256 + wrp * 32;
    float* xsw = &Xs[wrp][0];

    unsigned long long acc[8];
#pragma unroll
    for (int i = 0; i < 8; i++) acc[i] = 0ull;

    const float4* xg = reinterpret_cast<const float4*>(x);

    for (int kc = 0; kc < 64; kc++) {             // 64 chunks of 8 k
        // stage: 2 iterations x (16 rows, 2 float4/row) — coalesced
        int f4 = lane & 1;
#pragma unroll
        for (int it = 0; it < 2; it++) {
            int r = (lane >> 1) + it * 16;
            int grow = rbase + r;
            if (grow >= NNODES) grow = NNODES - 1;
            float4 v = __ldg(xg + (size_t)grow * 128 + kc * 2 + f4);
            float* dp = &xsw[r * XS_STRIDE + f4 * 4];
            dp[0] = v.x; dp[1] = v.y; dp[2] = v.z; dp[3] = v.w;
        }
        __syncwarp();

#pragma unroll
        for (int kb = 0; kb < 2; kb++) {
            float xvs[4];
#pragma unroll
            for (int d = 0; d < 4; d++)
                xvs[d] = xsw[lane * XS_STRIDE + kb * 4 + d];
#pragma unroll
            for (int d = 0; d < 4; d++) {
                int k = kc * 8 + kb * 4 + d;
                const float4* wr = reinterpret_cast<const float4*>(&Ws[k * 16]);
                float4 w0 = wr[0], w1 = wr[1], w2 = wr[2], w3 = wr[3];
                unsigned long long wp[8];
                wp[0] = *reinterpret_cast<unsigned long long*>(&w0.x);
                wp[1] = *reinterpret_cast<unsigned long long*>(&w0.z);
                wp[2] = *reinterpret_cast<unsigned long long*>(&w1.x);
                wp[3] = *reinterpret_cast<unsigned long long*>(&w1.z);
                wp[4] = *reinterpret_cast<unsigned long long*>(&w2.x);
                wp[5] = *reinterpret_cast<unsigned long long*>(&w2.z);
                wp[6] = *reinterpret_cast<unsigned long long*>(&w3.x);
                wp[7] = *reinterpret_cast<unsigned long long*>(&w3.z);
                unsigned long long xx;
                PACK2(xx, xvs[d]);
#pragma unroll
                for (int jp = 0; jp < 8; jp++)
                    FMA_F32X2(acc[jp], xx, wp[jp], acc[jp]);
            }
        }
        __syncwarp();
    }

    if (row < NNODES) {
        float4* o = reinterpret_cast<float4*>(g_h1 + (size_t)row * 16);
#pragma unroll
        for (int t = 0; t < 4; t++) {
            float2 lo = *reinterpret_cast<float2*>(&acc[t * 2]);
            float2 hi = *reinterpret_cast<float2*>(&acc[t * 2 + 1]);
            o[t] = make_float4(lo.x, lo.y, hi.x, hi.y);
        }
    }
}

// ---------------------------------------------------------------------------
// 2/3) CSR aggregation, warp per node (writes EVERY node -> no pre-zero).
// ---------------------------------------------------------------------------
template <int LAYER>
__global__ void agg_kernel(const float* __restrict__ b1) {
    int warp = (blockIdx.x * blockDim.x + threadIdx.x) >> 5;
    if (warp >= NNODES) return;
    int lane = threadIdx.x & 31;
    int q = lane >> 3;
    int j = lane & 7;

    int start = __ldg(&g_rowptr[warp]);
    int end   = __ldg(&g_rowptr[warp + 1]);

    float4 bq;
    if (LAYER == 2) bq = __ldg(reinterpret_cast<const float4*>(b1) + q);

    float4 acc = make_float4(0.f, 0.f, 0.f, 0.f);
    const float4* feat = reinterpret_cast<const float4*>(
        (LAYER == 1) ? g_h1 : g_agg1);

    for (int e = start + j; e < end; e += 8) {
        int s = __ldg(&g_esrc[e]);
        float4 v = __ldg(feat + (size_t)s * 4 + q);
        if (LAYER == 2) {
            v.x = fmaxf(v.x + bq.x, 0.f);
            v.y = fmaxf(v.y + bq.y, 0.f);
            v.z = fmaxf(v.z + bq.z, 0.f);
            v.w = fmaxf(v.w + bq.w, 0.f);
        }
        acc.x += v.x; acc.y += v.y; acc.z += v.z; acc.w += v.w;
    }

#pragma unroll
    for (int off = 4; off >= 1; off >>= 1) {
        acc.x += __shfl_xor_sync(0xffffffffu, acc.x, off);
        acc.y += __shfl_xor_sync(0xffffffffu, acc.y, off);
        acc.z += __shfl_xor_sync(0xffffffffu, acc.z, off);
        acc.w += __shfl_xor_sync(0xffffffffu, acc.w, off);
    }

    if (j == 0) {
        float* dst = (LAYER == 1) ? g_agg1 : g_agg2;
        reinterpret_cast<float4*>(dst + (size_t)warp * 16)[q] = acc;
    }
}

// ---------------------------------------------------------------------------
// 4) out = log_softmax(g_agg2 @ W2 + b2)
// ---------------------------------------------------------------------------
__global__ void final_kernel(const float* __restrict__ W2,
                             const float* __restrict__ b2,
                             float* __restrict__ out) {
    int i = blockIdx.x * blockDim.x + threadIdx.x;
    if (i >= NNODES) return;

    float a[16];
    const float4* ap = reinterpret_cast<const float4*>(g_agg2 + (size_t)i * 16);
#pragma unroll
    for (int t = 0; t < 4; t++) {
        float4 v = ap[t];
        a[t * 4 + 0] = v.x; a[t * 4 + 1] = v.y;
        a[t * 4 + 2] = v.z; a[t * 4 + 3] = v.w;
    }

    float v[40];
#pragma unroll
    for (int j = 0; j < 40; j++) v[j] = __ldg(b2 + j);
#pragma unroll
    for (int k = 0; k < 16; k++) {
        float ak = a[k];
#pragma unroll
        for (int j = 0; j < 40; j++)
            v[j] = fmaf(ak, __ldg(W2 + k * 40 + j), v[j]);
    }

    float m = v[0];
#pragma unroll
    for (int j = 1; j < 40; j++) m = fmaxf(m, v[j]);
    float ssum = 0.f;
#pragma unroll
    for (int j = 0; j < 40; j++) ssum += expf(v[j] - m);
    float lse = m + logf(ssum);

    float4* op = reinterpret_cast<float4*>(out + (size_t)i * 40);
#pragma unroll
    for (int t = 0; t < 10; t++)
        op[t] = make_float4(v[t*4+0] - lse, v[t*4+1] - lse,
                            v[t*4+2] - lse, v[t*4+3] - lse);
}

// ---------------------------------------------------------------------------
extern "C" void kernel_launch(void* const* d_in, const int* in_sizes, int n_in,
                              void* d_out, int out_size) {
    const float* x  = nullptr;
    const int*   ei = nullptr;
    const float* W1 = nullptr;
    const float* b1 = nullptr;
    const float* W2 = nullptr;
    const float* b2 = nullptr;

    for (int i = 0; i < n_in; i++) {
        int sz = in_sizes[i];
        if      (sz == 51200000)                   x  = (const float*)d_in[i];
        else if (sz == 6400000 || sz == 12800000)  ei = (const int*)d_in[i];
        else if (sz == 8192)                       W1 = (const float*)d_in[i];
        else if (sz == 16)                         b1 = (const float*)d_in[i];
        else if (sz == 640)                        W2 = (const float*)d_in[i];
        else if (sz == 40)                         b2 = (const float*)d_in[i];
    }

    const int E = NEDGES;
    float* out = (float*)d_out;

    detect_kernel<<<1, 256>>>(ei);                            // 1
    zero_cnt_kernel<<<(NNODES + 255) / 256, 256>>>();         // 2
    hist_kernel<<<(E + 255) / 256, 256>>>(ei, E);             // 3
    gemm1_kernel<<<391, 256>>>(x, W1);                        // 4  <- profiled
    scan1_kernel<<<NB_SCAN, 256>>>();                         // 5
    scan2_kernel<<<1, 512>>>();                               // 6
    scan3_kernel<<<(NNODES + 255) / 256, 256>>>();            // 7
    fill_kernel<<<(E + 255) / 256, 256>>>(ei, E);             // 8
    agg_kernel<1><<<(NNODES * 32 + 255) / 256, 256>>>(nullptr); // 9
    agg_kernel<2><<<(NNODES * 32 + 255) / 256, 256>>>(b1);    // 10
    final_kernel<<<(NNODES + 127) / 128, 128>>>(W2, b2, out); // 11
}